// round 14
// baseline (speedup 1.0000x reference)
#include <cuda_runtime.h>
#include <cuda_bf16.h>

// VectorQuantizer on GB300 — bit-exact fp32 emulation, single fused launch.
// R14: R11 tiling + epilogue of tile t software-pipelined into mainloop of t+1.
#define C_DIM   128
#define K_CODES 256
#define HW      4096
#define N_TOT   262144
#define BN      64
#define N_TILES (N_TOT / BN)     // 4096
#define NTH     256
#define NQ      33554432
#define GRID    148

// smem layout (floats)
#define E_OFF    0                        // embT [c][k] 32768
#define ZB_OFF   32768                    // 2 x 8192 raw z [buf][c][n]
#define SE_OFF   (ZB_OFF + 16384)         // 256
#define AP_OFF   (SE_OFF + 256)           // 256 partials
#define A_OFF    (AP_OFF + 256)           // 64
#define IDX_OFF  (A_OFF + 64)             // 64 ints
#define WS_OFF   (IDX_OFF + 64)           // 8
#define RED_OFF  (WS_OFF + 8)             // 1024 floats = 512 ull keys [w8][n64]
#define SMEM_FLOATS (RED_OFF + 1024)
#define SMEM_BYTES  (SMEM_FLOATS * 4)     // ~203 KB

__device__ double d_loss_arr[GRID];
__device__ int    d_done = 0;

// two independent IEEE-RN fma chains per instruction (lanes = adjacent k)
#define FMA2(d, a, b) asm("fma.rn.f32x2 %0, %1, %2, %0;" : "+l"(d) : "l"(a), "l"(b))

__device__ __forceinline__ unsigned long long dup2(float x) {
    unsigned long long r;
    unsigned u = __float_as_uint(x);
    asm("mov.b64 %0, {%1, %1};" : "=l"(r) : "r"(u));
    return r;
}

__device__ __forceinline__ void cp16(float* dst_smem, const float* src) {
    unsigned d = (unsigned)__cvta_generic_to_shared(dst_smem);
    asm volatile("cp.async.cg.shared.global [%0], [%1], 16;" :: "r"(d), "l"(src));
}
#define CP_COMMIT() asm volatile("cp.async.commit_group;")
#define CP_WAIT0()  asm volatile("cp.async.wait_group 0;")

// ---------------------------------------------------------------------------
__global__ void __launch_bounds__(NTH, 1)
vq_main(const float* __restrict__ z, const float* __restrict__ emb,
        float* __restrict__ out_q, float* __restrict__ out_idx,
        float* __restrict__ out_s) {
    extern __shared__ float smem[];
    float* e_s   = smem + E_OFF;
    float* zbuf0 = smem + ZB_OFF;
    float* zbuf1 = smem + ZB_OFF + 8192;
    float* se_s  = smem + SE_OFF;
    float* Ap    = smem + AP_OFF;
    float* A_s   = smem + A_OFF;
    int*   idx_s = (int*)(smem + IDX_OFF);
    float* wsum  = smem + WS_OFF;
    unsigned long long* red = (unsigned long long*)(smem + RED_OFF); // [8][64]

    const int tid  = threadIdx.x;
    const int lane = tid & 31, w = tid >> 5;

    // ---- prologue: build embT [c][k] + se in smem directly from gmem ----
    {
        int k = tid;
        const float4* er = (const float4*)(emb + (size_t)k * C_DIM);
        float s = 0.f;
        #pragma unroll 8
        for (int i = 0; i < 32; ++i) {
            float4 v = er[i];
            int c = i * 4;
            e_s[(c    ) * K_CODES + k] = v.x;
            e_s[(c + 1) * K_CODES + k] = v.y;
            e_s[(c + 2) * K_CODES + k] = v.z;
            e_s[(c + 3) * K_CODES + k] = v.w;
            s = __fmaf_rn(v.x, v.x, s); s = __fmaf_rn(v.y, v.y, s);
            s = __fmaf_rn(v.z, v.z, s); s = __fmaf_rn(v.w, v.w, s);
        }
        se_s[k] = s;   // sequential fused-fma chain, c ascending (R3 numerics)
    }

    // R11 tiling: warp w owns codes [32w, 32w+32); lane quad layout
    const int kq = lane & 3, nq = lane >> 2;
    const int n0 = nq * 8;
    const int k0 = w * 32 + kq * 8;
    float lsum_tot = 0.f;

    // ---- prefetch first z tile ----
    int tile = blockIdx.x;
    {
        int b = tile >> 6, hw0 = (tile & 63) << 6;
        const float* zb = z + (size_t)b * (C_DIM * HW) + hw0;
        #pragma unroll
        for (int i = 0; i < 8; ++i) {
            int idx = tid + i * NTH;
            int c = idx >> 4, n4 = (idx & 15) << 2;
            cp16(zbuf0 + c * 64 + n4, zb + (size_t)c * HW + n4);
        }
        CP_COMMIT();
    }

    int buf = 0;
    int pt = -1;                               // previous tile (epilogue pending)
    for (; tile < N_TILES; tile += GRID) {
        float* zcur = buf ? zbuf1 : zbuf0;
        float* znxt = buf ? zbuf0 : zbuf1;

        CP_WAIT0();
        __syncthreads();

        int next = tile + GRID;
        if (next < N_TILES) {
            int b = next >> 6, hw0 = (next & 63) << 6;
            const float* zb = z + (size_t)b * (C_DIM * HW) + hw0;
            #pragma unroll
            for (int i = 0; i < 8; ++i) {
                int idx = tid + i * NTH;
                int c = idx >> 4, n4 = (idx & 15) << 2;
                cp16(znxt + c * 64 + n4, zb + (size_t)c * HW + n4);
            }
            CP_COMMIT();
        }

        // ---- A_n via 4 partial fused-fma chains (argmin-invariant order) ----
        {
            int n = tid & 63, part = tid >> 6;
            const float* zp = zcur + part * 32 * 64 + n;
            float a = 0.f;
            #pragma unroll 8
            for (int c = 0; c < 32; ++c) { float v = zp[c * 64]; a = fmaf(v, v, a); }
            Ap[tid] = a;
        }
        __syncthreads();
        if (tid < 64)
            A_s[tid] = ((Ap[tid] + Ap[64 + tid]) + Ap[128 + tid]) + Ap[192 + tid];
        __syncthreads();

        // ---- mainloop (8 blocks of 16 c) with prev-tile epilogue chunks ----
        unsigned long long acc[8][4];
        #pragma unroll
        for (int i = 0; i < 8; ++i)
            #pragma unroll
            for (int j = 0; j < 4; ++j) acc[i][j] = 0ULL;

        const float* pzb = nullptr;
        float* pob = nullptr;
        float4 pzv;
        if (pt >= 0) {
            int pbb = pt >> 6, ph = (pt & 63) << 6;
            pzb = z + (size_t)pbb * (C_DIM * HW) + ph;     // L2-hot re-read
            pob = out_q + (size_t)pbb * (C_DIM * HW) + ph;
            int c = tid >> 4, n4 = (tid & 15) << 2;
            pzv = *(const float4*)(pzb + (size_t)c * HW + n4);
        }

        #pragma unroll 1
        for (int blk = 0; blk < 8; ++blk) {
            #pragma unroll 2
            for (int cc = 0; cc < 16; ++cc) {
                int c = blk * 16 + cc;
                const float4* zp = (const float4*)(zcur + c * 64 + n0);   // 4-way bcast
                float4 q0 = zp[0], q1 = zp[1];
                const ulonglong2* ep = (const ulonglong2*)(e_s + c * K_CODES + k0);
                ulonglong2 e0 = ep[0], e1 = ep[1];                        // 8-way bcast
                unsigned long long A8[8] = {dup2(q0.x), dup2(q0.y), dup2(q0.z), dup2(q0.w),
                                            dup2(q1.x), dup2(q1.y), dup2(q1.z), dup2(q1.w)};
                unsigned long long B4[4] = {e0.x, e0.y, e1.x, e1.y};
                #pragma unroll
                for (int j = 0; j < 4; ++j)
                    #pragma unroll
                    for (int i = 0; i < 8; ++i) FMA2(acc[i][j], A8[i], B4[j]);
            }
            if (pt >= 0) {   // one epilogue chunk for the previous tile
                int idx = tid + blk * NTH;
                int c = idx >> 4, n4 = (idx & 15) << 2;
                float4 zv = pzv;
                if (blk < 7) {   // rolling prefetch of next chunk's z
                    int idx2 = tid + (blk + 1) * NTH;
                    int c2 = idx2 >> 4, n42 = (idx2 & 15) << 2;
                    pzv = *(const float4*)(pzb + (size_t)c2 * HW + n42);
                }
                int ka = idx_s[n4], kb = idx_s[n4 + 1];
                int kc = idx_s[n4 + 2], kd = idx_s[n4 + 3];
                const float* ec = e_s + c * K_CODES;
                float d0 = ec[ka] - zv.x, d1 = ec[kb] - zv.y;
                float d2 = ec[kc] - zv.z, d3 = ec[kd] - zv.w;
                lsum_tot = fmaf(d0, d0, lsum_tot);
                lsum_tot = fmaf(d1, d1, lsum_tot);
                lsum_tot = fmaf(d2, d2, lsum_tot);
                lsum_tot = fmaf(d3, d3, lsum_tot);
                float4 o = make_float4(zv.x + d0, zv.y + d1, zv.z + d2, zv.w + d3);
                *(float4*)(pob + (size_t)c * HW + n4) = o;
            }
        }

        // ---- argmin: d = RN(RN(A - 2G) + se_k); quad-reduce then cross-warp ----
        #pragma unroll
        for (int i = 0; i < 8; ++i) {
            float An = A_s[n0 + i];
            unsigned long long best = 0ULL;
            #pragma unroll
            for (int j = 0; j < 4; ++j) {
                float2 g = *(float2*)&acc[i][j];
                int ka = k0 + 2 * j, kb = ka + 1;
                float da = __fadd_rn(__fadd_rn(An, -__fmul_rn(2.0f, g.x)), se_s[ka]);
                float db = __fadd_rn(__fadd_rn(An, -__fmul_rn(2.0f, g.y)), se_s[kb]);
                unsigned va = __float_as_uint(da);
                va = ((int)va < 0) ? ~va : (va | 0x80000000u);
                unsigned vb = __float_as_uint(db);
                vb = ((int)vb < 0) ? ~vb : (vb | 0x80000000u);
                unsigned long long keya = ((unsigned long long)(~va) << 32) | (unsigned)(255 - ka);
                unsigned long long keyb = ((unsigned long long)(~vb) << 32) | (unsigned)(255 - kb);
                if (keya > best) best = keya;
                if (keyb > best) best = keyb;
            }
            #pragma unroll
            for (int off = 1; off < 4; off <<= 1) {
                unsigned long long o = __shfl_xor_sync(0xFFFFFFFFu, best, off);
                if (o > best) best = o;
            }
            if (kq == 0) red[w * 64 + n0 + i] = best;
        }
        __syncthreads();          // also orders epilogue chunks before idx_s overwrite
        if (tid < 64) {
            unsigned long long best = red[tid];
            #pragma unroll
            for (int ww = 1; ww < 8; ++ww) {
                unsigned long long o = red[ww * 64 + tid];
                if (o > best) best = o;
            }
            idx_s[tid] = 255 - (int)(best & 0xFFFFFFFFull);
        }
        __syncthreads();
        if (out_idx != nullptr && tid < 64)
            out_idx[(size_t)tile * BN + tid] = (float)idx_s[tid];

        pt = tile;
        buf ^= 1;
    }

    // ---- standalone epilogue for the final tile ----
    if (pt >= 0) {
        int pbb = pt >> 6, ph = (pt & 63) << 6;
        const float* pzb = z + (size_t)pbb * (C_DIM * HW) + ph;
        float* pob = out_q + (size_t)pbb * (C_DIM * HW) + ph;
        #pragma unroll
        for (int blk = 0; blk < 8; ++blk) {
            int idx = tid + blk * NTH;
            int c = idx >> 4, n4 = (idx & 15) << 2;
            float4 zv = *(const float4*)(pzb + (size_t)c * HW + n4);
            int ka = idx_s[n4], kb = idx_s[n4 + 1];
            int kc = idx_s[n4 + 2], kd = idx_s[n4 + 3];
            const float* ec = e_s + c * K_CODES;
            float d0 = ec[ka] - zv.x, d1 = ec[kb] - zv.y;
            float d2 = ec[kc] - zv.z, d3 = ec[kd] - zv.w;
            lsum_tot = fmaf(d0, d0, lsum_tot);
            lsum_tot = fmaf(d1, d1, lsum_tot);
            lsum_tot = fmaf(d2, d2, lsum_tot);
            lsum_tot = fmaf(d3, d3, lsum_tot);
            float4 o = make_float4(zv.x + d0, zv.y + d1, zv.z + d2, zv.w + d3);
            *(float4*)(pob + (size_t)c * HW + n4) = o;
        }
    }

    // ---- per-CTA loss slot + last-block in-kernel finalize ----
    #pragma unroll
    for (int off = 16; off > 0; off >>= 1)
        lsum_tot += __shfl_xor_sync(0xFFFFFFFFu, lsum_tot, off);
    if (lane == 0) wsum[w] = lsum_tot;
    __syncthreads();
    if (tid == 0) {
        float t = 0.f;
        #pragma unroll
        for (int ww = 0; ww < 8; ++ww) t += wsum[ww];
        d_loss_arr[blockIdx.x] = (double)t;
        __threadfence();
        int old = atomicAdd(&d_done, 1);
        if (old == GRID - 1) {                 // last block: deterministic sum
            __threadfence();
            double s = 0.0;
            volatile double* la = d_loss_arr;
            for (int i = 0; i < GRID; ++i) s += la[i];
            double mse = s * (1.0 / (double)NQ);
            if (out_s != nullptr) {
                out_s[0] = (float)(0.25 * mse);
                out_s[1] = (float)mse;
            }
            d_done = 0;                        // reset for next graph replay
            __threadfence();
        }
    }
}

extern "C" void kernel_launch(void* const* d_in, const int* in_sizes, int n_in,
                              void* d_out, int out_size) {
    const float *z, *emb;
    if (n_in >= 2 && in_sizes[0] == K_CODES * C_DIM) {
        emb = (const float*)d_in[0];
        z   = (const float*)d_in[1];
    } else {
        z   = (const float*)d_in[0];
        emb = (const float*)d_in[1];
    }
    float* out = (float*)d_out;

    cudaFuncSetAttribute(vq_main, cudaFuncAttributeMaxDynamicSharedMemorySize,
                         SMEM_BYTES);

    float* out_idx = nullptr;
    float* out_s   = nullptr;
    long long osz = (long long)out_size;
    if (osz >= (long long)NQ + N_TOT)     out_idx = out + NQ;
    if (osz >= (long long)NQ + N_TOT + 2) out_s   = out + NQ + N_TOT;

    vq_main<<<GRID, NTH, SMEM_BYTES>>>(z, emb, out, out_idx, out_s);
}

// round 15
// speedup vs baseline: 1.1342x; 1.1342x over previous
#include <cuda_runtime.h>
#include <cuda_bf16.h>

// VectorQuantizer on GB300 — bit-exact fp32 emulation, single fused launch.
// R15: warp-specialized. Warps 0-7: untouched R11 FFMA2 GEMM + argmin.
//      Warps 8-11: epilogue(t-1) / A(t+1) / z staging, overlapped via named bars.
#define C_DIM   128
#define K_CODES 256
#define HW      4096
#define N_TOT   262144
#define BN      64
#define N_TILES (N_TOT / BN)     // 4096
#define NTH     384
#define NTH_G   256
#define NTH_H   128
#define NQ      33554432
#define GRID    148

// smem layout (floats)
#define E_OFF    0                        // embT [c][k] 32768
#define ZB_OFF   32768                    // 2 x 8192 raw z [buf][c][n]
#define SE_OFF   (ZB_OFF + 16384)         // 256
#define AB_OFF   (SE_OFF + 256)           // A[2][64]
#define APAR_OFF (AB_OFF + 128)           // Apar[128]
#define IDX_OFF  (APAR_OFF + 128)         // idx[2][64] ints
#define WS_OFF   (IDX_OFF + 128)          // 12
#define RED_OFF  (WS_OFF + 12)            // 1024 floats = 512 ull keys [w8][n64]
#define SMEM_FLOATS (RED_OFF + 1024)
#define SMEM_BYTES  (SMEM_FLOATS * 4)     // ~202 KB

__device__ double d_loss_arr[GRID];
__device__ int    d_done = 0;

#define FMA2(d, a, b) asm("fma.rn.f32x2 %0, %1, %2, %0;" : "+l"(d) : "l"(a), "l"(b))
#define BAR_SYNC(id, cnt)   asm volatile("bar.sync %0, %1;"   :: "r"(id), "r"(cnt) : "memory")
#define BAR_ARRIVE(id, cnt) asm volatile("bar.arrive %0, %1;" :: "r"(id), "r"(cnt) : "memory")

__device__ __forceinline__ unsigned long long dup2(float x) {
    unsigned long long r;
    unsigned u = __float_as_uint(x);
    asm("mov.b64 %0, {%1, %1};" : "=l"(r) : "r"(u));
    return r;
}
__device__ __forceinline__ void cp16(float* dst_smem, const float* src) {
    unsigned d = (unsigned)__cvta_generic_to_shared(dst_smem);
    asm volatile("cp.async.cg.shared.global [%0], [%1], 16;" :: "r"(d), "l"(src));
}
#define CP_COMMIT() asm volatile("cp.async.commit_group;")
#define CP_WAIT0()  asm volatile("cp.async.wait_group 0;")

// ---------------------------------------------------------------------------
__global__ void __launch_bounds__(NTH, 1)
vq_main(const float* __restrict__ z, const float* __restrict__ emb,
        float* __restrict__ out_q, float* __restrict__ out_idx,
        float* __restrict__ out_s) {
    extern __shared__ float smem[];
    float* e_s  = smem + E_OFF;
    float* zb   = smem + ZB_OFF;           // two 8192-float buffers
    float* se_s = smem + SE_OFF;
    float* Ab   = smem + AB_OFF;           // [2][64]
    float* Apar = smem + APAR_OFF;         // [128]
    int*   idxb = (int*)(smem + IDX_OFF);  // [2][64]
    float* wsum = smem + WS_OFF;
    unsigned long long* red = (unsigned long long*)(smem + RED_OFF); // [8][64]

    const int tid  = threadIdx.x;
    const int lane = tid & 31, w = tid >> 5;
    const int t0   = blockIdx.x;
    float lsum = 0.f;

    // ---- prologue ----
    if (tid < NTH_G) {       // embT [c][k] + se, sequential fused-fma (R3 numerics)
        int k = tid;
        const float4* er = (const float4*)(emb + (size_t)k * C_DIM);
        float s = 0.f;
        #pragma unroll 8
        for (int i = 0; i < 32; ++i) {
            float4 v = er[i];
            int c = i * 4;
            e_s[(c    ) * K_CODES + k] = v.x;
            e_s[(c + 1) * K_CODES + k] = v.y;
            e_s[(c + 2) * K_CODES + k] = v.z;
            e_s[(c + 3) * K_CODES + k] = v.w;
            s = __fmaf_rn(v.x, v.x, s); s = __fmaf_rn(v.y, v.y, s);
            s = __fmaf_rn(v.z, v.z, s); s = __fmaf_rn(v.w, v.w, s);
        }
        se_s[k] = s;
    }
    {   // z(t0) staged by all threads; each waits its own groups, then barrier
        int b = t0 >> 6, hw0 = (t0 & 63) << 6;
        const float* zp = z + (size_t)b * (C_DIM * HW) + hw0;
        for (int i = tid; i < 2048; i += NTH) {
            int c = i >> 4, n4 = (i & 15) << 2;
            cp16(zb + c * 64 + n4, zp + (size_t)c * HW + n4);
        }
        CP_COMMIT(); CP_WAIT0();
    }
    BAR_SYNC(0, NTH);
    if (tid >= NTH_G) {      // helpers pre-issue z(t1); they own all future groups
        int t1 = t0 + GRID;
        if (t1 < N_TILES) {
            int b = t1 >> 6, hw0 = (t1 & 63) << 6;
            const float* zp = z + (size_t)b * (C_DIM * HW) + hw0;
            for (int i = tid - NTH_G; i < 2048; i += NTH_H) {
                int c = i >> 4, n4 = (i & 15) << 2;
                cp16(zb + 8192 + c * 64 + n4, zp + (size_t)c * HW + n4);
            }
            CP_COMMIT();
        }
    }
    if (tid < 64) {          // A(t0): full 128-c fused-fma chain (argmin-invariant)
        float a = 0.f;
        const float* zp = zb + tid;
        #pragma unroll 8
        for (int c = 0; c < C_DIM; ++c) { float v = zp[c * 64]; a = __fmaf_rn(v, v, a); }
        Ab[tid] = a;
    }
    BAR_SYNC(0, NTH);

    // R11 tiling constants (GEMM warps)
    const int kq = lane & 3, nq = lane >> 2;
    const int n0 = nq * 8;
    const int k0 = w * 32 + kq * 8;

    int p = 0, pt = t0;
    for (int tile = t0; tile < N_TILES; tile += GRID) {
        pt = tile;
        if (tid < NTH_G) {
            // ============ GEMM warps: untouched R11 mainloop ============
            float* zcur = zb + p * 8192;
            unsigned long long acc[8][4];
            #pragma unroll
            for (int i = 0; i < 8; ++i)
                #pragma unroll
                for (int j = 0; j < 4; ++j) acc[i][j] = 0ULL;

            #pragma unroll 4
            for (int c = 0; c < C_DIM; ++c) {
                const float4* zp = (const float4*)(zcur + c * 64 + n0);
                float4 q0 = zp[0], q1 = zp[1];
                const ulonglong2* ep = (const ulonglong2*)(e_s + c * K_CODES + k0);
                ulonglong2 e0 = ep[0], e1 = ep[1];
                unsigned long long A8[8] = {dup2(q0.x), dup2(q0.y), dup2(q0.z), dup2(q0.w),
                                            dup2(q1.x), dup2(q1.y), dup2(q1.z), dup2(q1.w)};
                unsigned long long B4[4] = {e0.x, e0.y, e1.x, e1.y};
                #pragma unroll
                for (int j = 0; j < 4; ++j)
                    #pragma unroll
                    for (int i = 0; i < 8; ++i) FMA2(acc[i][j], A8[i], B4[j]);
            }
            BAR_ARRIVE(4, NTH);      // mainloop done: helpers may refill zcur

            // argmin: d = RN(RN(A - 2G) + se_k); quad-reduce then cross-warp
            const float* A_s = Ab + p * 64;
            #pragma unroll
            for (int i = 0; i < 8; ++i) {
                float An = A_s[n0 + i];
                unsigned long long best = 0ULL;
                #pragma unroll
                for (int j = 0; j < 4; ++j) {
                    float2 g = *(float2*)&acc[i][j];
                    int ka = k0 + 2 * j, kb = ka + 1;
                    float da = __fadd_rn(__fadd_rn(An, -__fmul_rn(2.0f, g.x)), se_s[ka]);
                    float db = __fadd_rn(__fadd_rn(An, -__fmul_rn(2.0f, g.y)), se_s[kb]);
                    unsigned va = __float_as_uint(da);
                    va = ((int)va < 0) ? ~va : (va | 0x80000000u);
                    unsigned vb = __float_as_uint(db);
                    vb = ((int)vb < 0) ? ~vb : (vb | 0x80000000u);
                    unsigned long long keya = ((unsigned long long)(~va) << 32) | (unsigned)(255 - ka);
                    unsigned long long keyb = ((unsigned long long)(~vb) << 32) | (unsigned)(255 - kb);
                    if (keya > best) best = keya;
                    if (keyb > best) best = keyb;
                }
                #pragma unroll
                for (int off = 1; off < 4; off <<= 1) {
                    unsigned long long o = __shfl_xor_sync(0xFFFFFFFFu, best, off);
                    if (o > best) best = o;
                }
                if (kq == 0) red[w * 64 + n0 + i] = best;
            }
            BAR_SYNC(3, NTH_G);
            if (tid < 64) {
                unsigned long long best = red[tid];
                #pragma unroll
                for (int ww = 1; ww < 8; ++ww) {
                    unsigned long long o = red[ww * 64 + tid];
                    if (o > best) best = o;
                }
                int ib = 255 - (int)(best & 0xFFFFFFFFull);
                idxb[p * 64 + tid] = ib;
                if (out_idx != nullptr)
                    out_idx[(size_t)tile * BN + tid] = (float)ib;
            }
        } else {
            // ============ helper warps ============
            int ht = tid - NTH_G;
            // 1. epilogue of previous tile (overlaps the GEMM mainloop)
            if (tile - GRID >= t0) {
                int ptile = tile - GRID;
                int b = ptile >> 6, hw0 = (ptile & 63) << 6;
                const float* pzb = z + (size_t)b * (C_DIM * HW) + hw0;   // L2-hot
                float* pob = out_q + (size_t)b * (C_DIM * HW) + hw0;
                const int* pidx = idxb + (p ^ 1) * 64;
                #pragma unroll 2
                for (int i = 0; i < 16; ++i) {
                    int idx = ht + i * NTH_H;
                    int c = idx >> 4, n4 = (idx & 15) << 2;
                    float4 zv = *(const float4*)(pzb + (size_t)c * HW + n4);
                    int ka = pidx[n4], kb = pidx[n4 + 1];
                    int kc = pidx[n4 + 2], kd = pidx[n4 + 3];
                    const float* ec = e_s + c * K_CODES;
                    float d0 = ec[ka] - zv.x, d1 = ec[kb] - zv.y;
                    float d2 = ec[kc] - zv.z, d3 = ec[kd] - zv.w;
                    lsum = __fmaf_rn(d0, d0, lsum); lsum = __fmaf_rn(d1, d1, lsum);
                    lsum = __fmaf_rn(d2, d2, lsum); lsum = __fmaf_rn(d3, d3, lsum);
                    float4 o = make_float4(zv.x + d0, zv.y + d1, zv.z + d2, zv.w + d3);
                    *(float4*)(pob + (size_t)c * HW + n4) = o;
                }
            }
            // 2+3. z(t+1) arrived -> compute A(t+1) into parity buffer
            CP_WAIT0();
            int nt = tile + GRID;
            if (nt < N_TILES) {
                int n = ht & 63, part = ht >> 6;           // 2 parts of 64 c
                const float* zp = zb + (p ^ 1) * 8192 + part * 64 * 64 + n;
                float a = 0.f;
                #pragma unroll 8
                for (int c = 0; c < 64; ++c) { float v = zp[c * 64]; a = __fmaf_rn(v, v, a); }
                Apar[ht] = a;
                BAR_SYNC(5, NTH_H);
                if (ht < 64) Ab[(p ^ 1) * 64 + ht] = Apar[ht] + Apar[64 + ht];
            }
            // 4. wait for mainloop(t) to release zcur, then refill with z(t+2)
            BAR_SYNC(4, NTH);
            int t2 = tile + 2 * GRID;
            if (t2 < N_TILES) {
                int b = t2 >> 6, hw0 = (t2 & 63) << 6;
                const float* zp = z + (size_t)b * (C_DIM * HW) + hw0;
                for (int i = ht; i < 2048; i += NTH_H) {
                    int c = i >> 4, n4 = (i & 15) << 2;
                    cp16(zb + p * 8192 + c * 64 + n4, zp + (size_t)c * HW + n4);
                }
                CP_COMMIT();
            }
        }
        BAR_SYNC(0, NTH);
        p ^= 1;
    }

    // ---- final tile epilogue (all threads) ----
    {
        int b = pt >> 6, hw0 = (pt & 63) << 6;
        const float* pzb = z + (size_t)b * (C_DIM * HW) + hw0;
        float* pob = out_q + (size_t)b * (C_DIM * HW) + hw0;
        const int* pidx = idxb + (p ^ 1) * 64;
        for (int i = tid; i < 2048; i += NTH) {
            int c = i >> 4, n4 = (i & 15) << 2;
            float4 zv = *(const float4*)(pzb + (size_t)c * HW + n4);
            int ka = pidx[n4], kb = pidx[n4 + 1];
            int kc = pidx[n4 + 2], kd = pidx[n4 + 3];
            const float* ec = e_s + c * K_CODES;
            float d0 = ec[ka] - zv.x, d1 = ec[kb] - zv.y;
            float d2 = ec[kc] - zv.z, d3 = ec[kd] - zv.w;
            lsum = __fmaf_rn(d0, d0, lsum); lsum = __fmaf_rn(d1, d1, lsum);
            lsum = __fmaf_rn(d2, d2, lsum); lsum = __fmaf_rn(d3, d3, lsum);
            float4 o = make_float4(zv.x + d0, zv.y + d1, zv.z + d2, zv.w + d3);
            *(float4*)(pob + (size_t)c * HW + n4) = o;
        }
    }
    BAR_SYNC(0, NTH);

    // ---- loss reduce -> per-CTA slot + last-block finalize ----
    #pragma unroll
    for (int off = 16; off > 0; off >>= 1)
        lsum += __shfl_xor_sync(0xFFFFFFFFu, lsum, off);
    if (lane == 0) wsum[w] = lsum;
    BAR_SYNC(0, NTH);
    if (tid == 0) {
        float t = 0.f;
        #pragma unroll
        for (int ww = 0; ww < 12; ++ww) t += wsum[ww];
        d_loss_arr[blockIdx.x] = (double)t;
        __threadfence();
        int old = atomicAdd(&d_done, 1);
        if (old == GRID - 1) {
            __threadfence();
            double s = 0.0;
            volatile double* la = d_loss_arr;
            for (int i = 0; i < GRID; ++i) s += la[i];
            double mse = s * (1.0 / (double)NQ);
            if (out_s != nullptr) {
                out_s[0] = (float)(0.25 * mse);
                out_s[1] = (float)mse;
            }
            d_done = 0;
            __threadfence();
        }
    }
}

extern "C" void kernel_launch(void* const* d_in, const int* in_sizes, int n_in,
                              void* d_out, int out_size) {
    const float *z, *emb;
    if (n_in >= 2 && in_sizes[0] == K_CODES * C_DIM) {
        emb = (const float*)d_in[0];
        z   = (const float*)d_in[1];
    } else {
        z   = (const float*)d_in[0];
        emb = (const float*)d_in[1];
    }
    float* out = (float*)d_out;

    cudaFuncSetAttribute(vq_main, cudaFuncAttributeMaxDynamicSharedMemorySize,
                         SMEM_BYTES);

    float* out_idx = nullptr;
    float* out_s   = nullptr;
    long long osz = (long long)out_size;
    if (osz >= (long long)NQ + N_TOT)     out_idx = out + NQ;
    if (osz >= (long long)NQ + N_TOT + 2) out_s   = out + NQ + N_TOT;

    vq_main<<<GRID, NTH, SMEM_BYTES>>>(z, emb, out, out_idx, out_s);
}

// round 16
// speedup vs baseline: 1.1685x; 1.0303x over previous
#include <cuda_runtime.h>
#include <cuda_bf16.h>

// VectorQuantizer on GB300 — bit-exact fp32 emulation, single fused launch.
// R16: R15 warp-specialization + slim argmin on GEMM warps (running min, one
//      key per n) + cross-warp combine moved to helper warps (double-buf red).
#define C_DIM   128
#define K_CODES 256
#define HW      4096
#define N_TOT   262144
#define BN      64
#define N_TILES (N_TOT / BN)     // 4096
#define NTH     384
#define NTH_G   256
#define NTH_H   128
#define NQ      33554432
#define GRID    148

// smem layout (floats)
#define E_OFF    0                        // embT [c][k] 32768
#define ZB_OFF   32768                    // 2 x 8192 raw z [buf][c][n]
#define SE_OFF   (ZB_OFF + 16384)         // 256
#define AB_OFF   (SE_OFF + 256)           // A[2][64]
#define APAR_OFF (AB_OFF + 128)           // Apar[128]
#define IDX_OFF  (APAR_OFF + 128)         // idx[2][64] ints
#define WS_OFF   (IDX_OFF + 128)          // 12 (+pad)
#define RED_OFF  (WS_OFF + 16)            // 2048 floats = red[2][512] ull keys
#define SMEM_FLOATS (RED_OFF + 2048)
#define SMEM_BYTES  (SMEM_FLOATS * 4)     // ~207 KB

__device__ double d_loss_arr[GRID];
__device__ int    d_done = 0;

#define FMA2(d, a, b) asm("fma.rn.f32x2 %0, %1, %2, %0;" : "+l"(d) : "l"(a), "l"(b))
#define BAR_SYNC(id, cnt)   asm volatile("bar.sync %0, %1;"   :: "r"(id), "r"(cnt) : "memory")
#define BAR_ARRIVE(id, cnt) asm volatile("bar.arrive %0, %1;" :: "r"(id), "r"(cnt) : "memory")

__device__ __forceinline__ unsigned long long dup2(float x) {
    unsigned long long r;
    unsigned u = __float_as_uint(x);
    asm("mov.b64 %0, {%1, %1};" : "=l"(r) : "r"(u));
    return r;
}
__device__ __forceinline__ void cp16(float* dst_smem, const float* src) {
    unsigned d = (unsigned)__cvta_generic_to_shared(dst_smem);
    asm volatile("cp.async.cg.shared.global [%0], [%1], 16;" :: "r"(d), "l"(src));
}
#define CP_COMMIT() asm volatile("cp.async.commit_group;")
#define CP_WAIT0()  asm volatile("cp.async.wait_group 0;")

// ---------------------------------------------------------------------------
__global__ void __launch_bounds__(NTH, 1)
vq_main(const float* __restrict__ z, const float* __restrict__ emb,
        float* __restrict__ out_q, float* __restrict__ out_idx,
        float* __restrict__ out_s) {
    extern __shared__ float smem[];
    float* e_s  = smem + E_OFF;
    float* zb   = smem + ZB_OFF;           // two 8192-float buffers
    float* se_s = smem + SE_OFF;
    float* Ab   = smem + AB_OFF;           // [2][64]
    float* Apar = smem + APAR_OFF;         // [128]
    int*   idxb = (int*)(smem + IDX_OFF);  // [2][64]
    float* wsum = smem + WS_OFF;
    unsigned long long* red = (unsigned long long*)(smem + RED_OFF); // [2][8][64]

    const int tid  = threadIdx.x;
    const int lane = tid & 31, w = tid >> 5;
    const int t0   = blockIdx.x;
    float lsum = 0.f;

    // ---- prologue ----
    if (tid < NTH_G) {       // embT [c][k] + se, sequential fused-fma (R3 numerics)
        int k = tid;
        const float4* er = (const float4*)(emb + (size_t)k * C_DIM);
        float s = 0.f;
        #pragma unroll 8
        for (int i = 0; i < 32; ++i) {
            float4 v = er[i];
            int c = i * 4;
            e_s[(c    ) * K_CODES + k] = v.x;
            e_s[(c + 1) * K_CODES + k] = v.y;
            e_s[(c + 2) * K_CODES + k] = v.z;
            e_s[(c + 3) * K_CODES + k] = v.w;
            s = __fmaf_rn(v.x, v.x, s); s = __fmaf_rn(v.y, v.y, s);
            s = __fmaf_rn(v.z, v.z, s); s = __fmaf_rn(v.w, v.w, s);
        }
        se_s[k] = s;
    }
    {   // z(t0) staged by all threads
        int b = t0 >> 6, hw0 = (t0 & 63) << 6;
        const float* zp = z + (size_t)b * (C_DIM * HW) + hw0;
        for (int i = tid; i < 2048; i += NTH) {
            int c = i >> 4, n4 = (i & 15) << 2;
            cp16(zb + c * 64 + n4, zp + (size_t)c * HW + n4);
        }
        CP_COMMIT(); CP_WAIT0();
    }
    BAR_SYNC(0, NTH);
    if (tid >= NTH_G) {      // helpers pre-issue z(t1); they own all future groups
        int t1 = t0 + GRID;
        if (t1 < N_TILES) {
            int b = t1 >> 6, hw0 = (t1 & 63) << 6;
            const float* zp = z + (size_t)b * (C_DIM * HW) + hw0;
            for (int i = tid - NTH_G; i < 2048; i += NTH_H) {
                int c = i >> 4, n4 = (i & 15) << 2;
                cp16(zb + 8192 + c * 64 + n4, zp + (size_t)c * HW + n4);
            }
            CP_COMMIT();
        }
    }
    if (tid < 64) {          // A(t0): full 128-c fused-fma chain (argmin-invariant)
        float a = 0.f;
        const float* zp = zb + tid;
        #pragma unroll 8
        for (int c = 0; c < C_DIM; ++c) { float v = zp[c * 64]; a = __fmaf_rn(v, v, a); }
        Ab[tid] = a;
    }
    BAR_SYNC(0, NTH);

    // R11 tiling constants (GEMM warps)
    const int kq = lane & 3, nq = lane >> 2;
    const int n0 = nq * 8;
    const int k0 = w * 32 + kq * 8;

    int p = 0, pt = t0;
    for (int tile = t0; tile < N_TILES; tile += GRID) {
        pt = tile;
        if (tid < NTH_G) {
            // ============ GEMM warps: untouched R11 mainloop ============
            float* zcur = zb + p * 8192;
            unsigned long long acc[8][4];
            #pragma unroll
            for (int i = 0; i < 8; ++i)
                #pragma unroll
                for (int j = 0; j < 4; ++j) acc[i][j] = 0ULL;

            #pragma unroll 4
            for (int c = 0; c < C_DIM; ++c) {
                const float4* zp = (const float4*)(zcur + c * 64 + n0);
                float4 q0 = zp[0], q1 = zp[1];
                const ulonglong2* ep = (const ulonglong2*)(e_s + c * K_CODES + k0);
                ulonglong2 e0 = ep[0], e1 = ep[1];
                unsigned long long A8[8] = {dup2(q0.x), dup2(q0.y), dup2(q0.z), dup2(q0.w),
                                            dup2(q1.x), dup2(q1.y), dup2(q1.z), dup2(q1.w)};
                unsigned long long B4[4] = {e0.x, e0.y, e1.x, e1.y};
                #pragma unroll
                for (int j = 0; j < 4; ++j)
                    #pragma unroll
                    for (int i = 0; i < 8; ++i) FMA2(acc[i][j], A8[i], B4[j]);
            }
            BAR_ARRIVE(4, NTH);      // mainloop done: helpers may refill zcur

            // slim argmin: running (min d, k) over ascending k, one key per n.
            // d = RN(RN(A - 2G) + se_k); strict < keeps first (smallest-k) min.
            const float* A_s = Ab + p * 64;
            #pragma unroll
            for (int i = 0; i < 8; ++i) {
                float An = A_s[n0 + i];
                float mn = 3.0e38f; int km = 0;
                #pragma unroll
                for (int j = 0; j < 4; ++j) {
                    float2 g = *(float2*)&acc[i][j];
                    int ka = k0 + 2 * j;
                    float da = __fadd_rn(__fadd_rn(An, -__fmul_rn(2.0f, g.x)), se_s[ka]);
                    if (da < mn) { mn = da; km = ka; }
                    float db = __fadd_rn(__fadd_rn(An, -__fmul_rn(2.0f, g.y)), se_s[ka + 1]);
                    if (db < mn) { mn = db; km = ka + 1; }
                }
                unsigned u = __float_as_uint(mn);
                u = ((int)u < 0) ? ~u : (u | 0x80000000u);   // order-preserving
                unsigned long long key = ((unsigned long long)u << 32) | (unsigned)km;
                #pragma unroll
                for (int off = 1; off < 4; off <<= 1) {      // quad (kq) min-reduce
                    unsigned long long o = __shfl_xor_sync(0xFFFFFFFFu, key, off);
                    if (o < key) key = o;
                }
                if (kq == 0) red[p * 512 + w * 64 + n0 + i] = key;
            }
        } else {
            // ============ helper warps ============
            int ht = tid - NTH_G;
            if (tile - GRID >= t0) {
                int ptile = tile - GRID;
                // 1. combine prev tile's per-warp keys -> idx + out_idx
                if (ht < 64) {
                    unsigned long long best = red[(p ^ 1) * 512 + ht];
                    #pragma unroll
                    for (int ww = 1; ww < 8; ++ww) {
                        unsigned long long o = red[(p ^ 1) * 512 + ww * 64 + ht];
                        if (o < best) best = o;
                    }
                    int ib = (int)(best & 255u);
                    idxb[(p ^ 1) * 64 + ht] = ib;
                    if (out_idx != nullptr)
                        out_idx[(size_t)ptile * BN + ht] = (float)ib;
                }
                BAR_SYNC(5, NTH_H);
                // 2. epilogue of prev tile (overlaps the GEMM mainloop)
                int b = ptile >> 6, hw0 = (ptile & 63) << 6;
                const float* pzb = z + (size_t)b * (C_DIM * HW) + hw0;   // L2-hot
                float* pob = out_q + (size_t)b * (C_DIM * HW) + hw0;
                const int* pidx = idxb + (p ^ 1) * 64;
                #pragma unroll 2
                for (int i = 0; i < 16; ++i) {
                    int idx = ht + i * NTH_H;
                    int c = idx >> 4, n4 = (idx & 15) << 2;
                    float4 zv = *(const float4*)(pzb + (size_t)c * HW + n4);
                    int ka = pidx[n4], kb = pidx[n4 + 1];
                    int kc = pidx[n4 + 2], kd = pidx[n4 + 3];
                    const float* ec = e_s + c * K_CODES;
                    float d0 = ec[ka] - zv.x, d1 = ec[kb] - zv.y;
                    float d2 = ec[kc] - zv.z, d3 = ec[kd] - zv.w;
                    lsum = __fmaf_rn(d0, d0, lsum); lsum = __fmaf_rn(d1, d1, lsum);
                    lsum = __fmaf_rn(d2, d2, lsum); lsum = __fmaf_rn(d3, d3, lsum);
                    float4 o = make_float4(zv.x + d0, zv.y + d1, zv.z + d2, zv.w + d3);
                    *(float4*)(pob + (size_t)c * HW + n4) = o;
                }
            }
            // 3. z(t+1) arrived -> compute A(t+1) into parity buffer
            CP_WAIT0();
            int nt = tile + GRID;
            if (nt < N_TILES) {
                int n = ht & 63, part = ht >> 6;           // 2 parts of 64 c
                const float* zp = zb + (p ^ 1) * 8192 + part * 64 * 64 + n;
                float a = 0.f;
                #pragma unroll 8
                for (int c = 0; c < 64; ++c) { float v = zp[c * 64]; a = __fmaf_rn(v, v, a); }
                Apar[ht] = a;
                BAR_SYNC(6, NTH_H);
                if (ht < 64) Ab[(p ^ 1) * 64 + ht] = Apar[ht] + Apar[64 + ht];
            }
            // 4. wait for mainloop(t) to release zcur, then refill with z(t+2)
            BAR_SYNC(4, NTH);
            int t2 = tile + 2 * GRID;
            if (t2 < N_TILES) {
                int b = t2 >> 6, hw0 = (t2 & 63) << 6;
                const float* zp = z + (size_t)b * (C_DIM * HW) + hw0;
                for (int i = ht; i < 2048; i += NTH_H) {
                    int c = i >> 4, n4 = (i & 15) << 2;
                    cp16(zb + p * 8192 + c * 64 + n4, zp + (size_t)c * HW + n4);
                }
                CP_COMMIT();
            }
        }
        BAR_SYNC(0, NTH);
        p ^= 1;
    }

    // ---- final tile: combine + epilogue (all threads) ----
    if (tid < 64) {
        unsigned long long best = red[(p ^ 1) * 512 + tid];
        #pragma unroll
        for (int ww = 1; ww < 8; ++ww) {
            unsigned long long o = red[(p ^ 1) * 512 + ww * 64 + tid];
            if (o < best) best = o;
        }
        int ib = (int)(best & 255u);
        idxb[(p ^ 1) * 64 + tid] = ib;
        if (out_idx != nullptr)
            out_idx[(size_t)pt * BN + tid] = (float)ib;
    }
    BAR_SYNC(0, NTH);
    {
        int b = pt >> 6, hw0 = (pt & 63) << 6;
        const float* pzb = z + (size_t)b * (C_DIM * HW) + hw0;
        float* pob = out_q + (size_t)b * (C_DIM * HW) + hw0;
        const int* pidx = idxb + (p ^ 1) * 64;
        for (int i = tid; i < 2048; i += NTH) {
            int c = i >> 4, n4 = (i & 15) << 2;
            float4 zv = *(const float4*)(pzb + (size_t)c * HW + n4);
            int ka = pidx[n4], kb = pidx[n4 + 1];
            int kc = pidx[n4 + 2], kd = pidx[n4 + 3];
            const float* ec = e_s + c * K_CODES;
            float d0 = ec[ka] - zv.x, d1 = ec[kb] - zv.y;
            float d2 = ec[kc] - zv.z, d3 = ec[kd] - zv.w;
            lsum = __fmaf_rn(d0, d0, lsum); lsum = __fmaf_rn(d1, d1, lsum);
            lsum = __fmaf_rn(d2, d2, lsum); lsum = __fmaf_rn(d3, d3, lsum);
            float4 o = make_float4(zv.x + d0, zv.y + d1, zv.z + d2, zv.w + d3);
            *(float4*)(pob + (size_t)c * HW + n4) = o;
        }
    }
    BAR_SYNC(0, NTH);

    // ---- loss reduce -> per-CTA slot + last-block finalize ----
    #pragma unroll
    for (int off = 16; off > 0; off >>= 1)
        lsum += __shfl_xor_sync(0xFFFFFFFFu, lsum, off);
    if (lane == 0) wsum[w] = lsum;
    BAR_SYNC(0, NTH);
    if (tid == 0) {
        float t = 0.f;
        #pragma unroll
        for (int ww = 0; ww < 12; ++ww) t += wsum[ww];
        d_loss_arr[blockIdx.x] = (double)t;
        __threadfence();
        int old = atomicAdd(&d_done, 1);
        if (old == GRID - 1) {
            __threadfence();
            double s = 0.0;
            volatile double* la = d_loss_arr;
            for (int i = 0; i < GRID; ++i) s += la[i];
            double mse = s * (1.0 / (double)NQ);
            if (out_s != nullptr) {
                out_s[0] = (float)(0.25 * mse);
                out_s[1] = (float)mse;
            }
            d_done = 0;
            __threadfence();
        }
    }
}

extern "C" void kernel_launch(void* const* d_in, const int* in_sizes, int n_in,
                              void* d_out, int out_size) {
    const float *z, *emb;
    if (n_in >= 2 && in_sizes[0] == K_CODES * C_DIM) {
        emb = (const float*)d_in[0];
        z   = (const float*)d_in[1];
    } else {
        z   = (const float*)d_in[0];
        emb = (const float*)d_in[1];
    }
    float* out = (float*)d_out;

    cudaFuncSetAttribute(vq_main, cudaFuncAttributeMaxDynamicSharedMemorySize,
                         SMEM_BYTES);

    float* out_idx = nullptr;
    float* out_s   = nullptr;
    long long osz = (long long)out_size;
    if (osz >= (long long)NQ + N_TOT)     out_idx = out + NQ;
    if (osz >= (long long)NQ + N_TOT + 2) out_s   = out + NQ + N_TOT;

    vq_main<<<GRID, NTH, SMEM_BYTES>>>(z, emb, out, out_idx, out_s);
}

// round 17
// speedup vs baseline: 1.2071x; 1.0330x over previous
#include <cuda_runtime.h>
#include <cuda_bf16.h>

// VectorQuantizer on GB300 — bit-exact fp32 emulation, single fused launch.
// R17: R16 + hoisted se regs + tournament-tree argmin (leftmost-tie, bit-exact).
#define C_DIM   128
#define K_CODES 256
#define HW      4096
#define N_TOT   262144
#define BN      64
#define N_TILES (N_TOT / BN)     // 4096
#define NTH     384
#define NTH_G   256
#define NTH_H   128
#define NQ      33554432
#define GRID    148

// smem layout (floats)
#define E_OFF    0                        // embT [c][k] 32768
#define ZB_OFF   32768                    // 2 x 8192 raw z [buf][c][n]
#define SE_OFF   (ZB_OFF + 16384)         // 256
#define AB_OFF   (SE_OFF + 256)           // A[2][64]
#define APAR_OFF (AB_OFF + 128)           // Apar[128]
#define IDX_OFF  (APAR_OFF + 128)         // idx[2][64] ints
#define WS_OFF   (IDX_OFF + 128)          // 12 (+pad)
#define RED_OFF  (WS_OFF + 16)            // 2048 floats = red[2][512] ull keys
#define SMEM_FLOATS (RED_OFF + 2048)
#define SMEM_BYTES  (SMEM_FLOATS * 4)     // ~207 KB

__device__ double d_loss_arr[GRID];
__device__ int    d_done = 0;

#define FMA2(d, a, b) asm("fma.rn.f32x2 %0, %1, %2, %0;" : "+l"(d) : "l"(a), "l"(b))
#define BAR_SYNC(id, cnt)   asm volatile("bar.sync %0, %1;"   :: "r"(id), "r"(cnt) : "memory")
#define BAR_ARRIVE(id, cnt) asm volatile("bar.arrive %0, %1;" :: "r"(id), "r"(cnt) : "memory")

__device__ __forceinline__ unsigned long long dup2(float x) {
    unsigned long long r;
    unsigned u = __float_as_uint(x);
    asm("mov.b64 %0, {%1, %1};" : "=l"(r) : "r"(u));
    return r;
}
__device__ __forceinline__ void cp16(float* dst_smem, const float* src) {
    unsigned d = (unsigned)__cvta_generic_to_shared(dst_smem);
    asm volatile("cp.async.cg.shared.global [%0], [%1], 16;" :: "r"(d), "l"(src));
}
#define CP_COMMIT() asm volatile("cp.async.commit_group;")
#define CP_WAIT0()  asm volatile("cp.async.wait_group 0;")

// ---------------------------------------------------------------------------
__global__ void __launch_bounds__(NTH, 1)
vq_main(const float* __restrict__ z, const float* __restrict__ emb,
        float* __restrict__ out_q, float* __restrict__ out_idx,
        float* __restrict__ out_s) {
    extern __shared__ float smem[];
    float* e_s  = smem + E_OFF;
    float* zb   = smem + ZB_OFF;           // two 8192-float buffers
    float* se_s = smem + SE_OFF;
    float* Ab   = smem + AB_OFF;           // [2][64]
    float* Apar = smem + APAR_OFF;         // [128]
    int*   idxb = (int*)(smem + IDX_OFF);  // [2][64]
    float* wsum = smem + WS_OFF;
    unsigned long long* red = (unsigned long long*)(smem + RED_OFF); // [2][8][64]

    const int tid  = threadIdx.x;
    const int lane = tid & 31, w = tid >> 5;
    const int t0   = blockIdx.x;
    float lsum = 0.f;

    // ---- prologue ----
    if (tid < NTH_G) {       // embT [c][k] + se, sequential fused-fma (R3 numerics)
        int k = tid;
        const float4* er = (const float4*)(emb + (size_t)k * C_DIM);
        float s = 0.f;
        #pragma unroll 8
        for (int i = 0; i < 32; ++i) {
            float4 v = er[i];
            int c = i * 4;
            e_s[(c    ) * K_CODES + k] = v.x;
            e_s[(c + 1) * K_CODES + k] = v.y;
            e_s[(c + 2) * K_CODES + k] = v.z;
            e_s[(c + 3) * K_CODES + k] = v.w;
            s = __fmaf_rn(v.x, v.x, s); s = __fmaf_rn(v.y, v.y, s);
            s = __fmaf_rn(v.z, v.z, s); s = __fmaf_rn(v.w, v.w, s);
        }
        se_s[k] = s;
    }
    {   // z(t0) staged by all threads
        int b = t0 >> 6, hw0 = (t0 & 63) << 6;
        const float* zp = z + (size_t)b * (C_DIM * HW) + hw0;
        for (int i = tid; i < 2048; i += NTH) {
            int c = i >> 4, n4 = (i & 15) << 2;
            cp16(zb + c * 64 + n4, zp + (size_t)c * HW + n4);
        }
        CP_COMMIT(); CP_WAIT0();
    }
    BAR_SYNC(0, NTH);
    if (tid >= NTH_G) {      // helpers pre-issue z(t1); they own all future groups
        int t1 = t0 + GRID;
        if (t1 < N_TILES) {
            int b = t1 >> 6, hw0 = (t1 & 63) << 6;
            const float* zp = z + (size_t)b * (C_DIM * HW) + hw0;
            for (int i = tid - NTH_G; i < 2048; i += NTH_H) {
                int c = i >> 4, n4 = (i & 15) << 2;
                cp16(zb + 8192 + c * 64 + n4, zp + (size_t)c * HW + n4);
            }
            CP_COMMIT();
        }
    }
    if (tid < 64) {          // A(t0): full 128-c fused-fma chain (argmin-invariant)
        float a = 0.f;
        const float* zp = zb + tid;
        #pragma unroll 8
        for (int c = 0; c < C_DIM; ++c) { float v = zp[c * 64]; a = __fmaf_rn(v, v, a); }
        Ab[tid] = a;
    }
    BAR_SYNC(0, NTH);

    // R11 tiling constants (GEMM warps)
    const int kq = lane & 3, nq = lane >> 2;
    const int n0 = nq * 8;
    const int k0 = w * 32 + kq * 8;

    // hoisted se for this thread's 8 codes (constant across tiles)
    float seR[8];
    if (tid < NTH_G) {
        #pragma unroll
        for (int j = 0; j < 4; ++j) {
            float2 s2 = *(const float2*)(se_s + k0 + 2 * j);
            seR[2 * j] = s2.x; seR[2 * j + 1] = s2.y;
        }
    }

    int p = 0, pt = t0;
    for (int tile = t0; tile < N_TILES; tile += GRID) {
        pt = tile;
        if (tid < NTH_G) {
            // ============ GEMM warps: untouched R11 mainloop ============
            float* zcur = zb + p * 8192;
            unsigned long long acc[8][4];
            #pragma unroll
            for (int i = 0; i < 8; ++i)
                #pragma unroll
                for (int j = 0; j < 4; ++j) acc[i][j] = 0ULL;

            #pragma unroll 4
            for (int c = 0; c < C_DIM; ++c) {
                const float4* zp = (const float4*)(zcur + c * 64 + n0);
                float4 q0 = zp[0], q1 = zp[1];
                const ulonglong2* ep = (const ulonglong2*)(e_s + c * K_CODES + k0);
                ulonglong2 e0 = ep[0], e1 = ep[1];
                unsigned long long A8[8] = {dup2(q0.x), dup2(q0.y), dup2(q0.z), dup2(q0.w),
                                            dup2(q1.x), dup2(q1.y), dup2(q1.z), dup2(q1.w)};
                unsigned long long B4[4] = {e0.x, e0.y, e1.x, e1.y};
                #pragma unroll
                for (int j = 0; j < 4; ++j)
                    #pragma unroll
                    for (int i = 0; i < 8; ++i) FMA2(acc[i][j], A8[i], B4[j]);
            }
            BAR_ARRIVE(4, NTH);      // mainloop done: helpers may refill zcur

            // argmin: d = RN(RN(A - 2G) + se_k); tournament tree (leftmost tie
            // = first-index min, identical selection to running-< over asc. k).
            const float* A_s = Ab + p * 64;
            #pragma unroll
            for (int i = 0; i < 8; ++i) {
                float An = A_s[n0 + i];
                float d[8];
                #pragma unroll
                for (int j = 0; j < 4; ++j) {
                    float2 g = *(float2*)&acc[i][j];
                    d[2 * j]     = __fadd_rn(__fadd_rn(An, -__fmul_rn(2.0f, g.x)), seR[2 * j]);
                    d[2 * j + 1] = __fadd_rn(__fadd_rn(An, -__fmul_rn(2.0f, g.y)), seR[2 * j + 1]);
                }
                // level 1 (pairs, ascending k; strict < keeps left on tie)
                float ma = (d[1] < d[0]) ? d[1] : d[0]; int ia = (d[1] < d[0]) ? 1 : 0;
                float mb = (d[3] < d[2]) ? d[3] : d[2]; int ib = (d[3] < d[2]) ? 3 : 2;
                float mc = (d[5] < d[4]) ? d[5] : d[4]; int ic = (d[5] < d[4]) ? 5 : 4;
                float md = (d[7] < d[6]) ? d[7] : d[6]; int id = (d[7] < d[6]) ? 7 : 6;
                // level 2
                float me = (mb < ma) ? mb : ma; int ie = (mb < ma) ? ib : ia;
                float mf = (md < mc) ? md : mc; int ig = (md < mc) ? id : ic;
                // level 3
                float mn = (mf < me) ? mf : me;
                int   km = k0 + ((mf < me) ? ig : ie);
                unsigned u = __float_as_uint(mn);
                u = ((int)u < 0) ? ~u : (u | 0x80000000u);   // order-preserving
                unsigned long long key = ((unsigned long long)u << 32) | (unsigned)km;
                #pragma unroll
                for (int off = 1; off < 4; off <<= 1) {      // quad (kq) min-reduce
                    unsigned long long o = __shfl_xor_sync(0xFFFFFFFFu, key, off);
                    if (o < key) key = o;
                }
                if (kq == 0) red[p * 512 + w * 64 + n0 + i] = key;
            }
        } else {
            // ============ helper warps ============
            int ht = tid - NTH_G;
            if (tile - GRID >= t0) {
                int ptile = tile - GRID;
                // 1. combine prev tile's per-warp keys -> idx + out_idx
                if (ht < 64) {
                    unsigned long long best = red[(p ^ 1) * 512 + ht];
                    #pragma unroll
                    for (int ww = 1; ww < 8; ++ww) {
                        unsigned long long o = red[(p ^ 1) * 512 + ww * 64 + ht];
                        if (o < best) best = o;
                    }
                    int ib = (int)(best & 255u);
                    idxb[(p ^ 1) * 64 + ht] = ib;
                    if (out_idx != nullptr)
                        out_idx[(size_t)ptile * BN + ht] = (float)ib;
                }
                BAR_SYNC(5, NTH_H);
                // 2. epilogue of prev tile (overlaps the GEMM mainloop)
                int b = ptile >> 6, hw0 = (ptile & 63) << 6;
                const float* pzb = z + (size_t)b * (C_DIM * HW) + hw0;   // L2-hot
                float* pob = out_q + (size_t)b * (C_DIM * HW) + hw0;
                const int* pidx = idxb + (p ^ 1) * 64;
                #pragma unroll 2
                for (int i = 0; i < 16; ++i) {
                    int idx = ht + i * NTH_H;
                    int c = idx >> 4, n4 = (idx & 15) << 2;
                    float4 zv = *(const float4*)(pzb + (size_t)c * HW + n4);
                    int ka = pidx[n4], kb = pidx[n4 + 1];
                    int kc = pidx[n4 + 2], kd = pidx[n4 + 3];
                    const float* ec = e_s + c * K_CODES;
                    float d0 = ec[ka] - zv.x, d1 = ec[kb] - zv.y;
                    float d2 = ec[kc] - zv.z, d3 = ec[kd] - zv.w;
                    lsum = __fmaf_rn(d0, d0, lsum); lsum = __fmaf_rn(d1, d1, lsum);
                    lsum = __fmaf_rn(d2, d2, lsum); lsum = __fmaf_rn(d3, d3, lsum);
                    float4 o = make_float4(zv.x + d0, zv.y + d1, zv.z + d2, zv.w + d3);
                    *(float4*)(pob + (size_t)c * HW + n4) = o;
                }
            }
            // 3. z(t+1) arrived -> compute A(t+1) into parity buffer
            CP_WAIT0();
            int nt = tile + GRID;
            if (nt < N_TILES) {
                int n = ht & 63, part = ht >> 6;           // 2 parts of 64 c
                const float* zp = zb + (p ^ 1) * 8192 + part * 64 * 64 + n;
                float a = 0.f;
                #pragma unroll 8
                for (int c = 0; c < 64; ++c) { float v = zp[c * 64]; a = __fmaf_rn(v, v, a); }
                Apar[ht] = a;
                BAR_SYNC(6, NTH_H);
                if (ht < 64) Ab[(p ^ 1) * 64 + ht] = Apar[ht] + Apar[64 + ht];
            }
            // 4. wait for mainloop(t) to release zcur, then refill with z(t+2)
            BAR_SYNC(4, NTH);
            int t2 = tile + 2 * GRID;
            if (t2 < N_TILES) {
                int b = t2 >> 6, hw0 = (t2 & 63) << 6;
                const float* zp = z + (size_t)b * (C_DIM * HW) + hw0;
                for (int i = ht; i < 2048; i += NTH_H) {
                    int c = i >> 4, n4 = (i & 15) << 2;
                    cp16(zb + p * 8192 + c * 64 + n4, zp + (size_t)c * HW + n4);
                }
                CP_COMMIT();
            }
        }
        BAR_SYNC(0, NTH);
        p ^= 1;
    }

    // ---- final tile: combine + epilogue (all threads) ----
    if (tid < 64) {
        unsigned long long best = red[(p ^ 1) * 512 + tid];
        #pragma unroll
        for (int ww = 1; ww < 8; ++ww) {
            unsigned long long o = red[(p ^ 1) * 512 + ww * 64 + tid];
            if (o < best) best = o;
        }
        int ib = (int)(best & 255u);
        idxb[(p ^ 1) * 64 + tid] = ib;
        if (out_idx != nullptr)
            out_idx[(size_t)pt * BN + tid] = (float)ib;
    }
    BAR_SYNC(0, NTH);
    {
        int b = pt >> 6, hw0 = (pt & 63) << 6;
        const float* pzb = z + (size_t)b * (C_DIM * HW) + hw0;
        float* pob = out_q + (size_t)b * (C_DIM * HW) + hw0;
        const int* pidx = idxb + (p ^ 1) * 64;
        for (int i = tid; i < 2048; i += NTH) {
            int c = i >> 4, n4 = (i & 15) << 2;
            float4 zv = *(const float4*)(pzb + (size_t)c * HW + n4);
            int ka = pidx[n4], kb = pidx[n4 + 1];
            int kc = pidx[n4 + 2], kd = pidx[n4 + 3];
            const float* ec = e_s + c * K_CODES;
            float d0 = ec[ka] - zv.x, d1 = ec[kb] - zv.y;
            float d2 = ec[kc] - zv.z, d3 = ec[kd] - zv.w;
            lsum = __fmaf_rn(d0, d0, lsum); lsum = __fmaf_rn(d1, d1, lsum);
            lsum = __fmaf_rn(d2, d2, lsum); lsum = __fmaf_rn(d3, d3, lsum);
            float4 o = make_float4(zv.x + d0, zv.y + d1, zv.z + d2, zv.w + d3);
            *(float4*)(pob + (size_t)c * HW + n4) = o;
        }
    }
    BAR_SYNC(0, NTH);

    // ---- loss reduce -> per-CTA slot + last-block finalize ----
    #pragma unroll
    for (int off = 16; off > 0; off >>= 1)
        lsum += __shfl_xor_sync(0xFFFFFFFFu, lsum, off);
    if (lane == 0) wsum[w] = lsum;
    BAR_SYNC(0, NTH);
    if (tid == 0) {
        float t = 0.f;
        #pragma unroll
        for (int ww = 0; ww < 12; ++ww) t += wsum[ww];
        d_loss_arr[blockIdx.x] = (double)t;
        __threadfence();
        int old = atomicAdd(&d_done, 1);
        if (old == GRID - 1) {
            __threadfence();
            double s = 0.0;
            volatile double* la = d_loss_arr;
            for (int i = 0; i < GRID; ++i) s += la[i];
            double mse = s * (1.0 / (double)NQ);
            if (out_s != nullptr) {
                out_s[0] = (float)(0.25 * mse);
                out_s[1] = (float)mse;
            }
            d_done = 0;
            __threadfence();
        }
    }
}

extern "C" void kernel_launch(void* const* d_in, const int* in_sizes, int n_in,
                              void* d_out, int out_size) {
    const float *z, *emb;
    if (n_in >= 2 && in_sizes[0] == K_CODES * C_DIM) {
        emb = (const float*)d_in[0];
        z   = (const float*)d_in[1];
    } else {
        z   = (const float*)d_in[0];
        emb = (const float*)d_in[1];
    }
    float* out = (float*)d_out;

    cudaFuncSetAttribute(vq_main, cudaFuncAttributeMaxDynamicSharedMemorySize,
                         SMEM_BYTES);

    float* out_idx = nullptr;
    float* out_s   = nullptr;
    long long osz = (long long)out_size;
    if (osz >= (long long)NQ + N_TOT)     out_idx = out + NQ;
    if (osz >= (long long)NQ + N_TOT + 2) out_s   = out + NQ + N_TOT;

    vq_main<<<GRID, NTH, SMEM_BYTES>>>(z, emb, out, out_idx, out_s);
}